// round 10
// baseline (speedup 1.0000x reference)
#include <cuda_runtime.h>
#include <cuda_bf16.h>

// ---------------------------------------------------------------------------
// GAT 3-layer + PairNorm. N=50000 nodes, E=800000 edges (+N self loops).
//   - CSR-by-dst per call: memset + hist -> fused scan+scatter (grid-resident),
//     which ALSO precomputes layer-1 edge softmax weights in the scatter tail.
//   - Per layer: tiled FP32 GEMM (f32x2 FMA) with fused PairNorm+ReLU A-load
//     and fused attention-coef epilogue -> edge-parallel weight precompute
//     (layers 2/3) -> single-pass softmax aggregation (warp-per-node,
//     precomputed weights, independent-lane loop, no float atomics) with
//     fused column-sum.
//   - Layer 3 fuses head-mean + bias, writes d_out directly.
// ---------------------------------------------------------------------------

#define MAXN 50000
#define MAXE 1000000   // E + N with margin

__device__ __align__(16) float g_xh[MAXN * 128];
__device__ __align__(16) float g_agg[MAXN * 128];
__device__ __align__(16) float g_als[MAXN * 2];
__device__ __align__(16) float g_ald[MAXN * 2];
__device__ __align__(16) float g_scale[MAXN];
__device__ __align__(16) float g_cs[2][128];
__device__ __align__(16) float2 g_w2[MAXE];
__device__ int g_cnt[MAXN + 1];
__device__ int g_off[MAXN + 1];
__device__ int g_cur[MAXN];
__device__ int g_csr[MAXE];
__device__ int g_dste[MAXE];
__device__ int g_bsum[256];
__device__ int g_bpre[256];
__device__ int g_sync[4];
__device__ int g_is64;

__device__ __forceinline__ int edge_val(const void* ei, int idx) {
    if (g_is64) return (int)((const long long*)ei)[idx];
    return ((const int*)ei)[idx];
}

__device__ __forceinline__ float lrelu(float x) { return fmaxf(x, 0.2f * x); }

__global__ void hist_kernel(const void* ei, int E, int Etot, int* cnt) {
    int e = blockIdx.x * blockDim.x + threadIdx.x;
    if (e >= Etot) return;
    int dst = (e < E) ? edge_val(ei, E + e) : (e - E);
    atomicAdd(&cnt[dst], 1);
}

// ---------------------------------------------------------------------------
// Fused scan + scatter + layer-1 edge-weight precompute. 196 blocks (all
// resident) -> flag-based grid barriers are deadlock-free. sync[] re-zeroed
// by a captured memset before each replay. The scatter tail also writes
// dste[] and w2[] (layer-1 weights) since src/dst/als/ald are all in hand.
// ---------------------------------------------------------------------------
__global__ void scanscatter_kernel(const int* __restrict__ cnt, int* __restrict__ off,
                                   int* __restrict__ cur, int* __restrict__ bsum,
                                   int* __restrict__ bpre, volatile int* sync, int n,
                                   const void* ei, int E, int Etot, int* __restrict__ csr,
                                   int* __restrict__ dste,
                                   const float* __restrict__ als,
                                   const float* __restrict__ ald,
                                   float2* __restrict__ w2) {
    __shared__ int sm[256];
    __shared__ int sm2[256];
    __shared__ int sflag;
    int t = threadIdx.x, b = blockIdx.x, nb = gridDim.x;
    int i = b * 256 + t;
    int v = (i < n) ? cnt[i] : 0;
    sm[t] = v;
    __syncthreads();
#pragma unroll
    for (int d = 1; d < 256; d <<= 1) {
        int x = (t >= d) ? sm[t - d] : 0;
        __syncthreads();
        sm[t] += x;
        __syncthreads();
    }
    if (t == 255) {
        bsum[b] = sm[255];
        __threadfence();
        int tk = atomicAdd((int*)&sync[0], 1);
        sflag = (tk == nb - 1);
    }
    __syncthreads();
    if (sflag) {  // last-arriving block scans the block sums
        int bv = (t < nb) ? bsum[t] : 0;
        sm2[t] = bv;
        __syncthreads();
#pragma unroll
        for (int d = 1; d < 256; d <<= 1) {
            int x = (t >= d) ? sm2[t - d] : 0;
            __syncthreads();
            sm2[t] += x;
            __syncthreads();
        }
        if (t < nb) bpre[t] = sm2[t] - bv;
        if (t == nb - 1) off[n] = sm2[t];
        __threadfence();
        if (t == 0) sync[1] = 1;
    }
    if (t == 0) {
        while (sync[1] == 0) __nanosleep(64);
        sflag = bpre[b];
    }
    __syncthreads();
    if (i < n) {
        int o = sflag + sm[t] - v;
        off[i] = o;
        cur[i] = o;
    }
    __threadfence();
    __syncthreads();
    if (t == 0) {
        atomicAdd((int*)&sync[2], 1);
        while (sync[2] < nb) __nanosleep(64);
    }
    __syncthreads();
    int nthreads = nb * 256;
    for (int e = b * 256 + t; e < Etot; e += nthreads) {
        int src, dst;
        if (e < E) { src = edge_val(ei, e); dst = edge_val(ei, E + e); }
        else       { src = dst = e - E; }
        int pos = atomicAdd(&cur[dst], 1);
        csr[pos] = src;
        dste[pos] = dst;
        float2 a = ((const float2*)als)[src];
        float2 d2 = ((const float2*)ald)[dst];
        w2[pos] = make_float2(__expf(lrelu(a.x + d2.x)), __expf(lrelu(a.y + d2.y)));
    }
}

// ---------------------------------------------------------------------------
// Edge-parallel weight precompute (layers 2/3): one thread per CSR slot.
// ---------------------------------------------------------------------------
__global__ void ew_kernel(const int* __restrict__ csr, const int* __restrict__ dste,
                          const float* __restrict__ als, const float* __restrict__ ald,
                          float2* __restrict__ w2, int Etot) {
    int e = blockIdx.x * blockDim.x + threadIdx.x;
    if (e >= Etot) return;
    int s = csr[e], d = dste[e];
    float2 a = ((const float2*)als)[s];
    float2 b = ((const float2*)ald)[d];
    w2[e] = make_float2(__expf(lrelu(a.x + b.x)), __expf(lrelu(a.y + b.y)));
}

// ---------------------------------------------------------------------------
// GEMM: C[N x OW] = act(A[N x 128]) * W[128 x OW], f32x2 packed FMA.
// If PN: act(v) = relu((v - mean[c]) * scale[row]) fused into A-tile load.
// Fused epilogue: als/ald per (row, head). Block 0 zeroes cs_zero and
// (if probe) detects edge dtype.
// ---------------------------------------------------------------------------
template <int OW, bool PN>
__global__ void __launch_bounds__(256)
gemm_attn_kernel(const float* __restrict__ A,
                 const float* __restrict__ mean_cs, const float* __restrict__ rscale,
                 const float* __restrict__ W,
                 const float* __restrict__ asrc, const float* __restrict__ adst,
                 float* __restrict__ C,
                 float* __restrict__ als, float* __restrict__ ald,
                 float* __restrict__ cs_zero, const void* ei_probe, int N) {
    constexpr int BK = 32;
    constexpr int BM = 64;
    constexpr int CT = OW / 8;
    constexpr int RT = 256 / CT;
    constexpr int RPT = BM / RT;
    __shared__ float As[BM][BK + 1];
    __shared__ float Ws[BK][OW];
    __shared__ float Ms[128];
    __shared__ float Ss[BM];
    __shared__ float Ps0[BM][CT], Pd0[BM][CT];
    __shared__ float Ps1[BM][CT], Pd1[BM][CT];
    int t = threadIdx.x;
    int tx = t % CT, ty = t / CT;
    int row0 = blockIdx.x * BM;

    if (cs_zero && blockIdx.x == 0 && t < 128) cs_zero[t] = 0.f;
    if (ei_probe && blockIdx.x == 0 && t < 32) {
        const long long* p = (const long long*)ei_probe;
        long long v = p[t];
        int ok = (v >= 0 && v < (long long)N);
        unsigned b = __ballot_sync(0xffffffffu, ok);
        if (t == 0) g_is64 = (b == 0xffffffffu) ? 1 : 0;
    }
    if (PN) {
        if (t < 128) Ms[t] = mean_cs[t] * (1.0f / (float)N);
        if (t >= 128 && t < 128 + BM) {
            int gr = row0 + t - 128;
            Ss[t - 128] = (gr < N) ? rscale[gr] : 0.f;
        }
        __syncthreads();
    }

    typedef unsigned long long u64;
    u64 acc2[RPT][4];
#pragma unroll
    for (int r = 0; r < RPT; r++)
#pragma unroll
        for (int j = 0; j < 4; j++) acc2[r][j] = 0ULL;

    for (int k0 = 0; k0 < 128; k0 += BK) {
        for (int i = t; i < BM * BK; i += 256) {
            int r = i / BK, c = i % BK;
            int gr = row0 + r;
            float v = (gr < N) ? A[(size_t)gr * 128 + k0 + c] : 0.f;
            if (PN) v = fmaxf((v - Ms[k0 + c]) * Ss[r], 0.f);
            As[r][c] = v;
        }
        for (int i = t; i < BK * OW; i += 256) {
            int r = i / OW, c = i % OW;
            Ws[r][c] = W[(k0 + r) * OW + c];
        }
        __syncthreads();
#pragma unroll
        for (int kk = 0; kk < BK; kk++) {
            u64 wv2[4];
#pragma unroll
            for (int j = 0; j < 4; j++)
                wv2[j] = *(const u64*)&Ws[kk][2 * tx + j * 2 * CT];
#pragma unroll
            for (int r = 0; r < RPT; r++) {
                float av = As[ty * RPT + r][kk];
                u64 av2;
                asm("mov.b64 %0, {%1, %1};" : "=l"(av2) : "f"(av));
#pragma unroll
                for (int j = 0; j < 4; j++)
                    asm("fma.rn.f32x2 %0, %1, %2, %0;" : "+l"(acc2[r][j]) : "l"(av2), "l"(wv2[j]));
            }
        }
        __syncthreads();
    }

    float2 av[4], bv[4];
#pragma unroll
    for (int j = 0; j < 4; j++) {
        av[j] = ((const float2*)asrc)[tx + j * CT];
        bv[j] = ((const float2*)adst)[tx + j * CT];
    }

#pragma unroll
    for (int r = 0; r < RPT; r++) {
        int row = ty * RPT + r;
        int gr = row0 + row;
        float s0 = 0.f, d0 = 0.f, s1 = 0.f, d1 = 0.f;
        float2 c2[4];
#pragma unroll
        for (int j = 0; j < 4; j++) {
            float lo, hi;
            asm("mov.b64 {%0, %1}, %2;" : "=f"(lo), "=f"(hi) : "l"(acc2[r][j]));
            c2[j] = make_float2(lo, hi);
            if (j < 2) {
                s0 = fmaf(lo, av[j].x, fmaf(hi, av[j].y, s0));
                d0 = fmaf(lo, bv[j].x, fmaf(hi, bv[j].y, d0));
            } else {
                s1 = fmaf(lo, av[j].x, fmaf(hi, av[j].y, s1));
                d1 = fmaf(lo, bv[j].x, fmaf(hi, bv[j].y, d1));
            }
        }
        Ps0[row][tx] = s0; Pd0[row][tx] = d0;
        Ps1[row][tx] = s1; Pd1[row][tx] = d1;
        if (gr < N) {
#pragma unroll
            for (int j = 0; j < 4; j++)
                ((float2*)&C[(size_t)gr * OW])[tx + j * CT] = c2[j];
        }
    }
    __syncthreads();
    if (t < BM * 2) {
        int row = t >> 1, h = t & 1;
        int gr = row0 + row;
        if (gr < N) {
            float s = 0.f, d = 0.f;
#pragma unroll
            for (int k = 0; k < CT; k++) {
                s += h ? Ps1[row][k] : Ps0[row][k];
                d += h ? Pd1[row][k] : Pd0[row][k];
            }
            als[gr * 2 + h] = s;
            ald[gr * 2 + h] = d;
        }
    }
}

// ---------------------------------------------------------------------------
// Single-pass softmax aggregation with PRECOMPUTED edge weights.
// Warp (or sub-warp) per destination node, independent-lane loop:
// per edge: csr broadcast + w2 broadcast + 2 FADD + select + LDG.128 + 4 FFMA.
// Fused column-sum (smem staging + 128 REDG).
// ---------------------------------------------------------------------------
template <int HD, bool FINAL>
__global__ void __launch_bounds__(256)
aggr_kernel(const float* __restrict__ xh,
            const float2* __restrict__ w2,
            const int* __restrict__ off, const int* __restrict__ csr,
            const float* __restrict__ bias,
            float* __restrict__ out, float* __restrict__ cs, int N) {
    constexpr int D = HD / 2;
    constexpr int L = HD / 4;          // lanes per node (32 or 8)
    constexpr int NPW = 32 / L;        // nodes per warp (1 or 4)
    int wib = threadIdx.x >> 5;
    int wid = blockIdx.x * 8 + wib;
    int lane = threadIdx.x & 31;
    int lig = lane % L;
    int nreq = wid * NPW + lane / L;
    bool valid = nreq < N;
    int n = valid ? nreq : (N - 1);

    int st = off[n], en = off[n + 1];
    int head = (lig * 4) / D;

    float s0 = 0.f, s1 = 0.f;
    float4 acc = make_float4(0.f, 0.f, 0.f, 0.f);
    const float4* x4 = (const float4*)xh;
#pragma unroll 4
    for (int i = st; i < en; i++) {
        int s = csr[i];
        float2 w = w2[i];
        s0 += w.x; s1 += w.y;
        float ws = head ? w.y : w.x;
        float4 v = x4[(size_t)s * L + lig];
        acc.x = fmaf(ws, v.x, acc.x);
        acc.y = fmaf(ws, v.y, acc.y);
        acc.z = fmaf(ws, v.z, acc.z);
        acc.w = fmaf(ws, v.w, acc.w);
    }
    float inv = 1.0f / (head ? s1 : s0);
    acc.x *= inv; acc.y *= inv; acc.z *= inv; acc.w *= inv;

    if (FINAL) {
        float ox = __shfl_down_sync(0xffffffffu, acc.x, 4);
        float oy = __shfl_down_sync(0xffffffffu, acc.y, 4);
        float oz = __shfl_down_sync(0xffffffffu, acc.z, 4);
        float ow = __shfl_down_sync(0xffffffffu, acc.w, 4);
        if (valid && lig < 4) {
            float4 r;
            r.x = 0.5f * (acc.x + ox) + bias[lig * 4 + 0];
            r.y = 0.5f * (acc.y + oy) + bias[lig * 4 + 1];
            r.z = 0.5f * (acc.z + oz) + bias[lig * 4 + 2];
            r.w = 0.5f * (acc.w + ow) + bias[lig * 4 + 3];
            ((float4*)out)[(size_t)n * 4 + lig] = r;
        }
    } else {
        if (valid) ((float4*)out)[(size_t)n * L + lig] = acc;
        __shared__ float csm[8][128];
        float4 a = valid ? acc : make_float4(0.f, 0.f, 0.f, 0.f);
        ((float4*)csm[wib])[lig] = a;
        __syncthreads();
        int t = threadIdx.x;
        if (t < 128) {
            float s = 0.f;
#pragma unroll
            for (int w = 0; w < 8; w++) s += csm[w][t];
            atomicAdd(&cs[t], s);
        }
    }
}

// ---------------------------------------------------------------------------
// Per-row PairNorm scale: scale[n] = 1/(eps + ||row - mean||)
// ---------------------------------------------------------------------------
__global__ void pnscale_kernel(const float* __restrict__ in, const float* __restrict__ cs,
                               float* __restrict__ scale, int N) {
    int wid = (blockIdx.x * blockDim.x + threadIdx.x) >> 5;
    int lane = threadIdx.x & 31;
    if (wid >= N) return;
    float invN = 1.0f / (float)N;
    float4 m = ((const float4*)cs)[lane];
    float4 v = ((const float4*)in)[(size_t)wid * 32 + lane];
    v.x -= m.x * invN; v.y -= m.y * invN; v.z -= m.z * invN; v.w -= m.w * invN;
    float n2 = v.x * v.x + v.y * v.y + v.z * v.z + v.w * v.w;
#pragma unroll
    for (int o = 16; o > 0; o >>= 1) n2 += __shfl_xor_sync(0xffffffffu, n2, o);
    if (lane == 0) scale[wid] = 1.0f / (1e-5f + sqrtf(n2));
}

// ---------------------------------------------------------------------------
extern "C" void kernel_launch(void* const* d_in, const int* in_sizes, int n_in,
                              void* d_out, int out_size) {
    const float* x   = (const float*)d_in[0];
    const void*  ei  = d_in[1];
    const float* W1  = (const float*)d_in[2];
    const float* as1 = (const float*)d_in[3];
    const float* ad1 = (const float*)d_in[4];
    const float* W2  = (const float*)d_in[6];
    const float* as2 = (const float*)d_in[7];
    const float* ad2 = (const float*)d_in[8];
    const float* W3  = (const float*)d_in[10];
    const float* as3 = (const float*)d_in[11];
    const float* ad3 = (const float*)d_in[12];
    const float* b3  = (const float*)d_in[13];

    int N = in_sizes[0] / 128;
    int E = in_sizes[1] / 2;
    int Etot = E + N;

    float *xh, *agg, *als, *ald, *scl, *cs;
    float2* w2;
    int *cnt, *off, *cur, *csr, *dste, *bsum, *bpre, *sync;
    cudaGetSymbolAddress((void**)&xh, g_xh);
    cudaGetSymbolAddress((void**)&agg, g_agg);
    cudaGetSymbolAddress((void**)&als, g_als);
    cudaGetSymbolAddress((void**)&ald, g_ald);
    cudaGetSymbolAddress((void**)&scl, g_scale);
    cudaGetSymbolAddress((void**)&cs, g_cs);
    cudaGetSymbolAddress((void**)&w2, g_w2);
    cudaGetSymbolAddress((void**)&cnt, g_cnt);
    cudaGetSymbolAddress((void**)&off, g_off);
    cudaGetSymbolAddress((void**)&cur, g_cur);
    cudaGetSymbolAddress((void**)&csr, g_csr);
    cudaGetSymbolAddress((void**)&dste, g_dste);
    cudaGetSymbolAddress((void**)&bsum, g_bsum);
    cudaGetSymbolAddress((void**)&bpre, g_bpre);
    cudaGetSymbolAddress((void**)&sync, g_sync);
    float* cs0 = cs;
    float* cs1 = cs + 128;

    const int TB = 256;
    int ewarp_blocks  = (N + 7) / 8;
    int ewarp_blocks4 = (N / 4 + 7) / 8;
    int gemm_blocks   = (N + 63) / 64;
    int nb1 = (N + 255) / 256;   // 196 <= 256 (residency requirement)

    // memset nodes (captured into the graph): counters + sync flags
    cudaMemsetAsync(cnt, 0, (size_t)N * sizeof(int));
    cudaMemsetAsync(sync, 0, 4 * sizeof(int));

    // ---- launch 0: GEMM layer 1 (embeds edge-dtype probe) ----
    gemm_attn_kernel<128, false><<<gemm_blocks, TB>>>(x, nullptr, nullptr, W1, as1, ad1,
                                                      xh, als, ald, cs0, ei, N);
    // ---- launch 1: histogram ----
    hist_kernel<<<(Etot + TB - 1) / TB, TB>>>(ei, E, Etot, cnt);
    // ---- launch 2: fused scan + scatter + layer-1 edge weights ----
    scanscatter_kernel<<<nb1, 256>>>(cnt, off, cur, bsum, bpre, sync, N, ei, E, Etot,
                                     csr, dste, als, ald, w2);
    // ---- launch 3: aggregation layer 1  <- ncu capture window ----
    aggr_kernel<128, false><<<ewarp_blocks, TB>>>(xh, w2, off, csr, nullptr, agg, cs0, N);
    pnscale_kernel<<<ewarp_blocks, TB>>>(agg, cs0, scl, N);

    // ---- layer 2 (PairNorm+ReLU fused into A-load) ----
    gemm_attn_kernel<128, true><<<gemm_blocks, TB>>>(agg, cs0, scl, W2, as2, ad2,
                                                     xh, als, ald, cs1, nullptr, N);
    ew_kernel<<<(Etot + TB - 1) / TB, TB>>>(csr, dste, als, ald, w2, Etot);
    aggr_kernel<128, false><<<ewarp_blocks, TB>>>(xh, w2, off, csr, nullptr, agg, cs1, N);
    pnscale_kernel<<<ewarp_blocks, TB>>>(agg, cs1, scl, N);

    // ---- layer 3 (writes d_out with head-mean + bias) ----
    gemm_attn_kernel<32, true><<<gemm_blocks, TB>>>(agg, cs1, scl, W3, as3, ad3,
                                                    xh, als, ald, nullptr, nullptr, N);
    ew_kernel<<<(Etot + TB - 1) / TB, TB>>>(csr, dste, als, ald, w2, Etot);
    aggr_kernel<32, true><<<ewarp_blocks4, TB>>>(xh, w2, off, csr, b3,
                                                 (float*)d_out, nullptr, N);
}

// round 11
// speedup vs baseline: 1.1421x; 1.1421x over previous
#include <cuda_runtime.h>
#include <cuda_bf16.h>
#include <cuda_fp16.h>

// ---------------------------------------------------------------------------
// GAT 3-layer + PairNorm. N=50000 nodes, E=800000 edges (+N self loops).
//   - CSR-by-dst per call: memset + hist(+dtype probe) -> 3-kernel decoupled
//     scan -> scatter (also writes dste + layer-1 edge softmax weights).
//   - Per layer: tiled FP32 GEMM (f32x2 FMA, fp16 feature output) with fused
//     PairNorm+ReLU A-load and fused attention-coef epilogue -> edge-parallel
//     weight precompute (layers 2/3) -> softmax aggregation with precomputed
//     weights, 16 lanes/node fp16 gathers (4 for layer 3), fused column-sum.
//   - Layer 3 fuses head-mean + bias, writes d_out directly.
// ---------------------------------------------------------------------------

#define MAXN 50000
#define MAXE 1000000   // E + N with margin

__device__ __align__(16) __half g_xh[MAXN * 128];
__device__ __align__(16) float g_agg[MAXN * 128];
__device__ __align__(16) float g_als[MAXN * 2];
__device__ __align__(16) float g_ald[MAXN * 2];
__device__ __align__(16) float g_scale[MAXN];
__device__ __align__(16) float g_cs[2][128];
__device__ __align__(16) float2 g_w2[MAXE];
__device__ int g_cnt[MAXN + 1];
__device__ int g_off[MAXN + 1];
__device__ int g_cur[MAXN];
__device__ int g_csr[MAXE];
__device__ int g_dste[MAXE];
__device__ int g_bsum[256];
__device__ int g_bpre[256];
__device__ int g_is64;

__device__ __forceinline__ int edge_val(const void* ei, int idx) {
    if (g_is64) return (int)((const long long*)ei)[idx];
    return ((const int*)ei)[idx];
}

__device__ __forceinline__ float lrelu(float x) { return fmaxf(x, 0.2f * x); }

// ---------------------------------------------------------------------------
// Histogram of destinations; embeds the edge-dtype probe (per-block shared
// flag; block 0 publishes g_is64 for the later scatter kernel).
// ---------------------------------------------------------------------------
__global__ void hist_kernel(const void* ei, int E, int Etot, int N, int* cnt) {
    __shared__ int sis64;
    if (threadIdx.x < 32) {
        const long long* p = (const long long*)ei;
        long long v = p[threadIdx.x];
        int ok = (v >= 0 && v < (long long)N);
        unsigned b = __ballot_sync(0xffffffffu, ok);
        if (threadIdx.x == 0) {
            sis64 = (b == 0xffffffffu) ? 1 : 0;
            if (blockIdx.x == 0) g_is64 = sis64;
        }
    }
    __syncthreads();
    int e = blockIdx.x * blockDim.x + threadIdx.x;
    if (e >= Etot) return;
    int dst;
    if (e < E) dst = sis64 ? (int)((const long long*)ei)[E + e] : ((const int*)ei)[E + e];
    else       dst = e - E;
    atomicAdd(&cnt[dst], 1);
}

// ---------------------------------------------------------------------------
// Decoupled 3-kernel scan (R4-measured fastest CSR path)
// ---------------------------------------------------------------------------
__global__ void scan_bsum_kernel(const int* __restrict__ cnt, int* __restrict__ bsum, int n) {
    int t = threadIdx.x;
    int i = blockIdx.x * 256 + t;
    int v = (i < n) ? cnt[i] : 0;
#pragma unroll
    for (int o = 16; o > 0; o >>= 1) v += __shfl_down_sync(0xffffffffu, v, o);
    __shared__ int ws[8];
    if ((t & 31) == 0) ws[t >> 5] = v;
    __syncthreads();
    if (t == 0) {
        int s = 0;
#pragma unroll
        for (int w = 0; w < 8; w++) s += ws[w];
        bsum[blockIdx.x] = s;
    }
}

__global__ void scan_bscan_kernel(const int* __restrict__ bsum, int* __restrict__ bpre,
                                  int* __restrict__ off, int nb, int n) {
    __shared__ int sm[256];
    int t = threadIdx.x;
    int v = (t < nb) ? bsum[t] : 0;
    sm[t] = v;
    __syncthreads();
#pragma unroll
    for (int d = 1; d < 256; d <<= 1) {
        int x = (t >= d) ? sm[t - d] : 0;
        __syncthreads();
        sm[t] += x;
        __syncthreads();
    }
    if (t < nb) bpre[t] = sm[t] - v;
    if (t == 255) off[n] = sm[255];
}

__global__ void scan_write_kernel(const int* __restrict__ cnt, const int* __restrict__ bpre,
                                  int* __restrict__ off, int* __restrict__ cur, int n) {
    __shared__ int sm[256];
    int t = threadIdx.x;
    int i = blockIdx.x * 256 + t;
    int v = (i < n) ? cnt[i] : 0;
    sm[t] = v;
    __syncthreads();
#pragma unroll
    for (int d = 1; d < 256; d <<= 1) {
        int x = (t >= d) ? sm[t - d] : 0;
        __syncthreads();
        sm[t] += x;
        __syncthreads();
    }
    if (i < n) {
        int o = bpre[blockIdx.x] + sm[t] - v;
        off[i] = o;
        cur[i] = o;
    }
}

// ---------------------------------------------------------------------------
// Scatter edges into CSR; also writes dste[] and layer-1 softmax weights.
// ---------------------------------------------------------------------------
__global__ void scatter_kernel(const void* ei, int E, int Etot, int* cur,
                               int* __restrict__ csr, int* __restrict__ dste,
                               const float* __restrict__ als, const float* __restrict__ ald,
                               float2* __restrict__ w2) {
    int e = blockIdx.x * blockDim.x + threadIdx.x;
    if (e >= Etot) return;
    int src, dst;
    if (e < E) { src = edge_val(ei, e); dst = edge_val(ei, E + e); }
    else       { src = dst = e - E; }
    int pos = atomicAdd(&cur[dst], 1);
    csr[pos] = src;
    dste[pos] = dst;
    float2 a = ((const float2*)als)[src];
    float2 d2 = ((const float2*)ald)[dst];
    w2[pos] = make_float2(__expf(lrelu(a.x + d2.x)), __expf(lrelu(a.y + d2.y)));
}

// ---------------------------------------------------------------------------
// Edge-parallel weight precompute (layers 2/3)
// ---------------------------------------------------------------------------
__global__ void ew_kernel(const int* __restrict__ csr, const int* __restrict__ dste,
                          const float* __restrict__ als, const float* __restrict__ ald,
                          float2* __restrict__ w2, int Etot) {
    int e = blockIdx.x * blockDim.x + threadIdx.x;
    if (e >= Etot) return;
    int s = csr[e], d = dste[e];
    float2 a = ((const float2*)als)[s];
    float2 b = ((const float2*)ald)[d];
    w2[e] = make_float2(__expf(lrelu(a.x + b.x)), __expf(lrelu(a.y + b.y)));
}

// ---------------------------------------------------------------------------
// GEMM: C[N x OW](fp16) = act(A[N x 128]) * W[128 x OW], f32x2 packed FMA.
// If PN: act(v) = relu((v - mean[c]) * scale[row]) fused into A-tile load.
// Fused epilogue: als/ald per (row, head). Block 0 zeroes cs_zero[0:128).
// ---------------------------------------------------------------------------
template <int OW, bool PN>
__global__ void __launch_bounds__(256)
gemm_attn_kernel(const float* __restrict__ A,
                 const float* __restrict__ mean_cs, const float* __restrict__ rscale,
                 const float* __restrict__ W,
                 const float* __restrict__ asrc, const float* __restrict__ adst,
                 __half* __restrict__ C,
                 float* __restrict__ als, float* __restrict__ ald,
                 float* __restrict__ cs_zero, int N) {
    constexpr int BK = 32;
    constexpr int BM = 64;
    constexpr int CT = OW / 8;
    constexpr int RT = 256 / CT;
    constexpr int RPT = BM / RT;
    __shared__ float As[BM][BK + 1];
    __shared__ float Ws[BK][OW];
    __shared__ float Ms[128];
    __shared__ float Ss[BM];
    __shared__ float Ps0[BM][CT], Pd0[BM][CT];
    __shared__ float Ps1[BM][CT], Pd1[BM][CT];
    int t = threadIdx.x;
    int tx = t % CT, ty = t / CT;
    int row0 = blockIdx.x * BM;

    if (cs_zero && blockIdx.x == 0 && t < 128) cs_zero[t] = 0.f;
    if (PN) {
        if (t < 128) Ms[t] = mean_cs[t] * (1.0f / (float)N);
        if (t >= 128 && t < 128 + BM) {
            int gr = row0 + t - 128;
            Ss[t - 128] = (gr < N) ? rscale[gr] : 0.f;
        }
        __syncthreads();
    }

    typedef unsigned long long u64;
    u64 acc2[RPT][4];
#pragma unroll
    for (int r = 0; r < RPT; r++)
#pragma unroll
        for (int j = 0; j < 4; j++) acc2[r][j] = 0ULL;

    for (int k0 = 0; k0 < 128; k0 += BK) {
        for (int i = t; i < BM * BK; i += 256) {
            int r = i / BK, c = i % BK;
            int gr = row0 + r;
            float v = (gr < N) ? A[(size_t)gr * 128 + k0 + c] : 0.f;
            if (PN) v = fmaxf((v - Ms[k0 + c]) * Ss[r], 0.f);
            As[r][c] = v;
        }
        for (int i = t; i < BK * OW; i += 256) {
            int r = i / OW, c = i % OW;
            Ws[r][c] = W[(k0 + r) * OW + c];
        }
        __syncthreads();
#pragma unroll
        for (int kk = 0; kk < BK; kk++) {
            u64 wv2[4];
#pragma unroll
            for (int j = 0; j < 4; j++)
                wv2[j] = *(const u64*)&Ws[kk][2 * tx + j * 2 * CT];
#pragma unroll
            for (int r = 0; r < RPT; r++) {
                float av = As[ty * RPT + r][kk];
                u64 av2;
                asm("mov.b64 %0, {%1, %1};" : "=l"(av2) : "f"(av));
#pragma unroll
                for (int j = 0; j < 4; j++)
                    asm("fma.rn.f32x2 %0, %1, %2, %0;" : "+l"(acc2[r][j]) : "l"(av2), "l"(wv2[j]));
            }
        }
        __syncthreads();
    }

    float2 av[4], bv[4];
#pragma unroll
    for (int j = 0; j < 4; j++) {
        av[j] = ((const float2*)asrc)[tx + j * CT];
        bv[j] = ((const float2*)adst)[tx + j * CT];
    }

#pragma unroll
    for (int r = 0; r < RPT; r++) {
        int row = ty * RPT + r;
        int gr = row0 + row;
        float s0 = 0.f, d0 = 0.f, s1 = 0.f, d1 = 0.f;
        __half2 c2[4];
#pragma unroll
        for (int j = 0; j < 4; j++) {
            float lo, hi;
            asm("mov.b64 {%0, %1}, %2;" : "=f"(lo), "=f"(hi) : "l"(acc2[r][j]));
            c2[j] = __float22half2_rn(make_float2(lo, hi));
            if (j < 2) {
                s0 = fmaf(lo, av[j].x, fmaf(hi, av[j].y, s0));
                d0 = fmaf(lo, bv[j].x, fmaf(hi, bv[j].y, d0));
            } else {
                s1 = fmaf(lo, av[j].x, fmaf(hi, av[j].y, s1));
                d1 = fmaf(lo, bv[j].x, fmaf(hi, bv[j].y, d1));
            }
        }
        Ps0[row][tx] = s0; Pd0[row][tx] = d0;
        Ps1[row][tx] = s1; Pd1[row][tx] = d1;
        if (gr < N) {
#pragma unroll
            for (int j = 0; j < 4; j++)
                ((__half2*)&C[(size_t)gr * OW])[tx + j * CT] = c2[j];
        }
    }
    __syncthreads();
    if (t < BM * 2) {
        int row = t >> 1, h = t & 1;
        int gr = row0 + row;
        if (gr < N) {
            float s = 0.f, d = 0.f;
#pragma unroll
            for (int k = 0; k < CT; k++) {
                s += h ? Ps1[row][k] : Ps0[row][k];
                d += h ? Pd1[row][k] : Pd0[row][k];
            }
            als[gr * 2 + h] = s;
            ald[gr * 2 + h] = d;
        }
    }
}

// ---------------------------------------------------------------------------
// Softmax aggregation, precomputed weights, fp16 features, 16B per lane:
// HD=128: L=16 lanes/node (uint4 = 8 halves each), 2 nodes/warp.
// HD=32 (FINAL): L=4 lanes/node, 8 nodes/warp; head-mean + bias -> d_out.
// Weight sums are replicated across subgroup lanes (no reduction needed).
// Fused column-sum for non-FINAL layers.
// ---------------------------------------------------------------------------
template <int HD, bool FINAL>
__global__ void __launch_bounds__(256)
aggr_kernel(const __half* __restrict__ xh,
            const float2* __restrict__ w2,
            const int* __restrict__ off, const int* __restrict__ csr,
            const float* __restrict__ bias,
            float* __restrict__ out, float* __restrict__ cs, int N) {
    constexpr int L = (HD * 2) / 16;   // lanes per node: 16 (HD=128) or 4 (HD=32)
    constexpr int NPW = 32 / L;        // nodes per warp: 2 or 8
    constexpr int D = HD / 2;          // features per head
    int wib = threadIdx.x >> 5;
    int wid = blockIdx.x * 8 + wib;
    int lane = threadIdx.x & 31;
    int sub = lane / L;
    int lig = lane % L;
    int nreq = wid * NPW + sub;
    bool valid = nreq < N;
    int n = valid ? nreq : (N - 1);

    int st = off[n], en = off[n + 1];
    int head = (lig * 8) / D;          // 8 features per lane

    float s0 = 0.f, s1 = 0.f;
    float acc[8];
#pragma unroll
    for (int k = 0; k < 8; k++) acc[k] = 0.f;
    const uint4* x16 = (const uint4*)xh;   // row stride = L uint4s

#pragma unroll 4
    for (int i = st; i < en; i++) {
        int s = csr[i];
        float2 w = w2[i];
        s0 += w.x; s1 += w.y;
        float ws = head ? w.y : w.x;
        uint4 u = x16[(size_t)s * L + lig];
        float2 f0 = __half22float2(*(__half2*)&u.x);
        float2 f1 = __half22float2(*(__half2*)&u.y);
        float2 f2 = __half22float2(*(__half2*)&u.z);
        float2 f3 = __half22float2(*(__half2*)&u.w);
        acc[0] = fmaf(ws, f0.x, acc[0]);
        acc[1] = fmaf(ws, f0.y, acc[1]);
        acc[2] = fmaf(ws, f1.x, acc[2]);
        acc[3] = fmaf(ws, f1.y, acc[3]);
        acc[4] = fmaf(ws, f2.x, acc[4]);
        acc[5] = fmaf(ws, f2.y, acc[5]);
        acc[6] = fmaf(ws, f3.x, acc[6]);
        acc[7] = fmaf(ws, f3.y, acc[7]);
    }
    float inv = 1.0f / (head ? s1 : s0);
#pragma unroll
    for (int k = 0; k < 8; k++) acc[k] *= inv;

    if (FINAL) {
        // L=4: lanes lig<2 hold head0 feats, lig>=2 head1 (partner = lane+2).
        float o[8];
#pragma unroll
        for (int k = 0; k < 8; k++) o[k] = __shfl_down_sync(0xffffffffu, acc[k], 2);
        if (valid && lig < 2) {
            float4 r0, r1;
            r0.x = 0.5f * (acc[0] + o[0]) + bias[lig * 8 + 0];
            r0.y = 0.5f * (acc[1] + o[1]) + bias[lig * 8 + 1];
            r0.z = 0.5f * (acc[2] + o[2]) + bias[lig * 8 + 2];
            r0.w = 0.5f * (acc[3] + o[3]) + bias[lig * 8 + 3];
            r1.x = 0.5f * (acc[4] + o[4]) + bias[lig * 8 + 4];
            r1.y = 0.5f * (acc[5] + o[5]) + bias[lig * 8 + 5];
            r1.z = 0.5f * (acc[6] + o[6]) + bias[lig * 8 + 6];
            r1.w = 0.5f * (acc[7] + o[7]) + bias[lig * 8 + 7];
            float4* dst = (float4*)&out[(size_t)n * 16 + lig * 8];
            dst[0] = r0;
            dst[1] = r1;
        }
    } else {
        if (valid) {
            float4* dst = (float4*)&out[(size_t)n * 128 + lig * 8];
            dst[0] = make_float4(acc[0], acc[1], acc[2], acc[3]);
            dst[1] = make_float4(acc[4], acc[5], acc[6], acc[7]);
        }
        // fused column-sum: 16 node rows staged in smem, 128 threads reduce
        __shared__ float csm[16][128];
        float* rowp = csm[wib * 2 + sub];
        if (!valid) {
#pragma unroll
            for (int k = 0; k < 8; k++) acc[k] = 0.f;
        }
        ((float4*)&rowp[lig * 8])[0] = make_float4(acc[0], acc[1], acc[2], acc[3]);
        ((float4*)&rowp[lig * 8])[1] = make_float4(acc[4], acc[5], acc[6], acc[7]);
        __syncthreads();
        int t = threadIdx.x;
        if (t < 128) {
            float s = 0.f;
#pragma unroll
            for (int w = 0; w < 16; w++) s += csm[w][t];
            atomicAdd(&cs[t], s);
        }
    }
}

// ---------------------------------------------------------------------------
// Per-row PairNorm scale: scale[n] = 1/(eps + ||row - mean||)
// ---------------------------------------------------------------------------
__global__ void pnscale_kernel(const float* __restrict__ in, const float* __restrict__ cs,
                               float* __restrict__ scale, int N) {
    int wid = (blockIdx.x * blockDim.x + threadIdx.x) >> 5;
    int lane = threadIdx.x & 31;
    if (wid >= N) return;
    float invN = 1.0f / (float)N;
    float4 m = ((const float4*)cs)[lane];
    float4 v = ((const float4*)in)[(size_t)wid * 32 + lane];
    v.x -= m.x * invN; v.y -= m.y * invN; v.z -= m.z * invN; v.w -= m.w * invN;
    float n2 = v.x * v.x + v.y * v.y + v.z * v.z + v.w * v.w;
#pragma unroll
    for (int o = 16; o > 0; o >>= 1) n2 += __shfl_xor_sync(0xffffffffu, n2, o);
    if (lane == 0) scale[wid] = 1.0f / (1e-5f + sqrtf(n2));
}

// ---------------------------------------------------------------------------
extern "C" void kernel_launch(void* const* d_in, const int* in_sizes, int n_in,
                              void* d_out, int out_size) {
    const float* x   = (const float*)d_in[0];
    const void*  ei  = d_in[1];
    const float* W1  = (const float*)d_in[2];
    const float* as1 = (const float*)d_in[3];
    const float* ad1 = (const float*)d_in[4];
    const float* W2  = (const float*)d_in[6];
    const float* as2 = (const float*)d_in[7];
    const float* ad2 = (const float*)d_in[8];
    const float* W3  = (const float*)d_in[10];
    const float* as3 = (const float*)d_in[11];
    const float* ad3 = (const float*)d_in[12];
    const float* b3  = (const float*)d_in[13];

    int N = in_sizes[0] / 128;
    int E = in_sizes[1] / 2;
    int Etot = E + N;

    __half* xh;
    float *agg, *als, *ald, *scl, *cs;
    float2* w2;
    int *cnt, *off, *cur, *csr, *dste, *bsum, *bpre;
    cudaGetSymbolAddress((void**)&xh, g_xh);
    cudaGetSymbolAddress((void**)&agg, g_agg);
    cudaGetSymbolAddress((void**)&als, g_als);
    cudaGetSymbolAddress((void**)&ald, g_ald);
    cudaGetSymbolAddress((void**)&scl, g_scale);
    cudaGetSymbolAddress((void**)&cs, g_cs);
    cudaGetSymbolAddress((void**)&w2, g_w2);
    cudaGetSymbolAddress((void**)&cnt, g_cnt);
    cudaGetSymbolAddress((void**)&off, g_off);
    cudaGetSymbolAddress((void**)&cur, g_cur);
    cudaGetSymbolAddress((void**)&csr, g_csr);
    cudaGetSymbolAddress((void**)&dste, g_dste);
    cudaGetSymbolAddress((void**)&bsum, g_bsum);
    cudaGetSymbolAddress((void**)&bpre, g_bpre);
    float* cs0 = cs;
    float* cs1 = cs + 128;

    const int TB = 256;
    int aggr_blocks   = (N / 2 + 7) / 8;   // 2 nodes/warp, 8 warps/block
    int aggr_blocks8  = (N / 8 + 7) / 8;   // 8 nodes/warp (layer 3)
    int pn_blocks     = (N + 7) / 8;
    int gemm_blocks   = (N + 63) / 64;
    int nb1 = (N + 255) / 256;             // 196 <= 256

    cudaMemsetAsync(cnt, 0, (size_t)N * sizeof(int));

    // ---- launch 0: histogram (embeds dtype probe) ----
    hist_kernel<<<(Etot + TB - 1) / TB, TB>>>(ei, E, Etot, N, cnt);
    // ---- launches 1-2: scan front ----
    scan_bsum_kernel<<<nb1, 256>>>(cnt, bsum, N);
    scan_bscan_kernel<<<1, 256>>>(bsum, bpre, off, nb1, N);
    // ---- launch 3: GEMM layer 1  <- ncu capture window ----
    gemm_attn_kernel<128, false><<<gemm_blocks, TB>>>(x, nullptr, nullptr, W1, as1, ad1,
                                                      xh, als, ald, cs0, N);
    // ---- launches 4-5: finish CSR (scatter also computes layer-1 weights) ----
    scan_write_kernel<<<nb1, 256>>>(cnt, bpre, off, cur, N);
    scatter_kernel<<<(Etot + TB - 1) / TB, TB>>>(ei, E, Etot, cur, csr, dste, als, ald, w2);

    // ---- layer 1 aggregation + pairnorm scale ----
    aggr_kernel<128, false><<<aggr_blocks, TB>>>(xh, w2, off, csr, nullptr, agg, cs0, N);
    pnscale_kernel<<<pn_blocks, TB>>>(agg, cs0, scl, N);

    // ---- layer 2 ----
    gemm_attn_kernel<128, true><<<gemm_blocks, TB>>>(agg, cs0, scl, W2, as2, ad2,
                                                     xh, als, ald, cs1, N);
    ew_kernel<<<(Etot + TB - 1) / TB, TB>>>(csr, dste, als, ald, w2, Etot);
    aggr_kernel<128, false><<<aggr_blocks, TB>>>(xh, w2, off, csr, nullptr, agg, cs1, N);
    pnscale_kernel<<<pn_blocks, TB>>>(agg, cs1, scl, N);

    // ---- layer 3 (writes d_out with head-mean + bias) ----
    gemm_attn_kernel<32, true><<<gemm_blocks, TB>>>(agg, cs1, scl, W3, as3, ad3,
                                                    xh, als, ald, nullptr, N);
    ew_kernel<<<(Etot + TB - 1) / TB, TB>>>(csr, dste, als, ald, w2, Etot);
    aggr_kernel<32, true><<<aggr_blocks8, TB>>>(xh, w2, off, csr, b3,
                                                (float*)d_out, nullptr, N);
}

// round 12
// speedup vs baseline: 1.2791x; 1.1199x over previous
#include <cuda_runtime.h>
#include <cuda_bf16.h>
#include <cuda_fp16.h>

// ---------------------------------------------------------------------------
// GAT 3-layer + PairNorm. N=50000 nodes, E=800000 edges (+N self loops).
//   - CSR-by-dst per call: memset + hist(+dtype probe) -> 3-kernel decoupled
//     scan -> scatter (also writes dste + layer-1 edge softmax weights).
//   - Per layer: 128x128-tile FP32 GEMM (f32x2 FMA, transposed pre-duplicated
//     A tile, 8x8 per thread) with fused PairNorm+ReLU A-load and shuffle-
//     reduced attention-coef epilogue, fp16 feature output -> edge-parallel
//     weight precompute (layers 2/3) -> softmax aggregation with precomputed
//     weights, 16 lanes/node fp16 gathers (4 for layer 3), fused column-sum.
//   - Layer 3 fuses head-mean + bias, writes d_out directly.
// ---------------------------------------------------------------------------

#define MAXN 50000
#define MAXE 1000000   // E + N with margin

__device__ __align__(16) __half g_xh[MAXN * 128];
__device__ __align__(16) float g_agg[MAXN * 128];
__device__ __align__(16) float g_als[MAXN * 2];
__device__ __align__(16) float g_ald[MAXN * 2];
__device__ __align__(16) float g_scale[MAXN];
__device__ __align__(16) float g_cs[2][128];
__device__ __align__(16) float2 g_w2[MAXE];
__device__ int g_cnt[MAXN + 1];
__device__ int g_off[MAXN + 1];
__device__ int g_cur[MAXN];
__device__ int g_csr[MAXE];
__device__ int g_dste[MAXE];
__device__ int g_bsum[256];
__device__ int g_bpre[256];
__device__ int g_is64;

__device__ __forceinline__ int edge_val(const void* ei, int idx) {
    if (g_is64) return (int)((const long long*)ei)[idx];
    return ((const int*)ei)[idx];
}

__device__ __forceinline__ float lrelu(float x) { return fmaxf(x, 0.2f * x); }

// ---------------------------------------------------------------------------
// Histogram of destinations; embeds the edge-dtype probe.
// ---------------------------------------------------------------------------
__global__ void hist_kernel(const void* ei, int E, int Etot, int N, int* cnt) {
    __shared__ int sis64;
    if (threadIdx.x < 32) {
        const long long* p = (const long long*)ei;
        long long v = p[threadIdx.x];
        int ok = (v >= 0 && v < (long long)N);
        unsigned b = __ballot_sync(0xffffffffu, ok);
        if (threadIdx.x == 0) {
            sis64 = (b == 0xffffffffu) ? 1 : 0;
            if (blockIdx.x == 0) g_is64 = sis64;
        }
    }
    __syncthreads();
    int e = blockIdx.x * blockDim.x + threadIdx.x;
    if (e >= Etot) return;
    int dst;
    if (e < E) dst = sis64 ? (int)((const long long*)ei)[E + e] : ((const int*)ei)[E + e];
    else       dst = e - E;
    atomicAdd(&cnt[dst], 1);
}

// ---------------------------------------------------------------------------
// Decoupled 3-kernel scan
// ---------------------------------------------------------------------------
__global__ void scan_bsum_kernel(const int* __restrict__ cnt, int* __restrict__ bsum, int n) {
    int t = threadIdx.x;
    int i = blockIdx.x * 256 + t;
    int v = (i < n) ? cnt[i] : 0;
#pragma unroll
    for (int o = 16; o > 0; o >>= 1) v += __shfl_down_sync(0xffffffffu, v, o);
    __shared__ int ws[8];
    if ((t & 31) == 0) ws[t >> 5] = v;
    __syncthreads();
    if (t == 0) {
        int s = 0;
#pragma unroll
        for (int w = 0; w < 8; w++) s += ws[w];
        bsum[blockIdx.x] = s;
    }
}

__global__ void scan_bscan_kernel(const int* __restrict__ bsum, int* __restrict__ bpre,
                                  int* __restrict__ off, int nb, int n) {
    __shared__ int sm[256];
    int t = threadIdx.x;
    int v = (t < nb) ? bsum[t] : 0;
    sm[t] = v;
    __syncthreads();
#pragma unroll
    for (int d = 1; d < 256; d <<= 1) {
        int x = (t >= d) ? sm[t - d] : 0;
        __syncthreads();
        sm[t] += x;
        __syncthreads();
    }
    if (t < nb) bpre[t] = sm[t] - v;
    if (t == 255) off[n] = sm[255];
}

__global__ void scan_write_kernel(const int* __restrict__ cnt, const int* __restrict__ bpre,
                                  int* __restrict__ off, int* __restrict__ cur, int n) {
    __shared__ int sm[256];
    int t = threadIdx.x;
    int i = blockIdx.x * 256 + t;
    int v = (i < n) ? cnt[i] : 0;
    sm[t] = v;
    __syncthreads();
#pragma unroll
    for (int d = 1; d < 256; d <<= 1) {
        int x = (t >= d) ? sm[t - d] : 0;
        __syncthreads();
        sm[t] += x;
        __syncthreads();
    }
    if (i < n) {
        int o = bpre[blockIdx.x] + sm[t] - v;
        off[i] = o;
        cur[i] = o;
    }
}

// ---------------------------------------------------------------------------
// Scatter edges into CSR; also writes dste[] and layer-1 softmax weights.
// ---------------------------------------------------------------------------
__global__ void scatter_kernel(const void* ei, int E, int Etot, int* cur,
                               int* __restrict__ csr, int* __restrict__ dste,
                               const float* __restrict__ als, const float* __restrict__ ald,
                               float2* __restrict__ w2) {
    int e = blockIdx.x * blockDim.x + threadIdx.x;
    if (e >= Etot) return;
    int src, dst;
    if (e < E) { src = edge_val(ei, e); dst = edge_val(ei, E + e); }
    else       { src = dst = e - E; }
    int pos = atomicAdd(&cur[dst], 1);
    csr[pos] = src;
    dste[pos] = dst;
    float2 a = ((const float2*)als)[src];
    float2 d2 = ((const float2*)ald)[dst];
    w2[pos] = make_float2(__expf(lrelu(a.x + d2.x)), __expf(lrelu(a.y + d2.y)));
}

// ---------------------------------------------------------------------------
// Edge-parallel weight precompute (layers 2/3)
// ---------------------------------------------------------------------------
__global__ void ew_kernel(const int* __restrict__ csr, const int* __restrict__ dste,
                          const float* __restrict__ als, const float* __restrict__ ald,
                          float2* __restrict__ w2, int Etot) {
    int e = blockIdx.x * blockDim.x + threadIdx.x;
    if (e >= Etot) return;
    int s = csr[e], d = dste[e];
    float2 a = ((const float2*)als)[s];
    float2 b = ((const float2*)ald)[d];
    w2[e] = make_float2(__expf(lrelu(a.x + b.x)), __expf(lrelu(a.y + b.y)));
}

// ---------------------------------------------------------------------------
// GEMM: C[N x OW](fp16) = act(A[N x 128]) * W[128 x OW].
// 128x128 block tile (BMxOW), BK=16, 256 threads, 8 rows x 4 col-pairs per
// thread, f32x2 packed FMA. A tile stored transposed + pre-duplicated {v,v}
// in As2[kk][row] -> inner loop reads 4 LDS.128 + 4 LDS.64 per kk for 32
// FFMA2. If PN: act(v)=relu((v-mean[c])*scale[row]) fused into A load.
// Attention-coef epilogue reduced via width-CT shuffles (no smem partials).
// Block 0 zeroes cs_zero[0:128).
// ---------------------------------------------------------------------------
template <int OW, bool PN>
__global__ void __launch_bounds__(256, 2)
gemm_attn_kernel(const float* __restrict__ A,
                 const float* __restrict__ mean_cs, const float* __restrict__ rscale,
                 const float* __restrict__ W,
                 const float* __restrict__ asrc, const float* __restrict__ adst,
                 __half* __restrict__ C,
                 float* __restrict__ als, float* __restrict__ ald,
                 float* __restrict__ cs_zero, int N) {
    constexpr int BK = 16;
    constexpr int BM = 128;
    constexpr int CT = OW / 8;        // threads along cols (16 or 4)
    constexpr int RT = 256 / CT;      // threads along rows (16 or 64)
    constexpr int RPT = BM / RT;      // rows per thread (8 or 2)
    typedef unsigned long long u64;
    __shared__ __align__(16) u64 As2[BK][BM + 2];   // transposed, pre-dup {v,v}
    __shared__ float Ws[BK][OW];
    __shared__ float Ms[128];
    __shared__ float Ss[BM];
    int t = threadIdx.x;
    int tx = t % CT, ty = t / CT;
    int row0 = blockIdx.x * BM;

    if (cs_zero && blockIdx.x == 0 && t < 128) cs_zero[t] = 0.f;
    if (PN) {
        if (t < 128) Ms[t] = mean_cs[t] * (1.0f / (float)N);
        if (t >= 128) {
            int gr = row0 + t - 128;
            Ss[t - 128] = (gr < N) ? rscale[gr] : 0.f;
        }
        __syncthreads();
    }

    u64 acc2[RPT][4];
#pragma unroll
    for (int r = 0; r < RPT; r++)
#pragma unroll
        for (int j = 0; j < 4; j++) acc2[r][j] = 0ULL;

    for (int k0 = 0; k0 < 128; k0 += BK) {
        // A tile: 128 rows x 16 cols, float4 loads, transpose + dup into As2
#pragma unroll
        for (int i = 0; i < 2; i++) {
            int idx = t + i * 256;          // 0..511 float4 slots
            int r = idx >> 2;               // row in tile
            int c4 = idx & 3;               // float4 within 16 cols
            int gr = row0 + r;
            float4 v = (gr < N) ? ((const float4*)A)[(size_t)gr * 32 + (k0 >> 2) + c4]
                                : make_float4(0.f, 0.f, 0.f, 0.f);
            if (PN) {
                float sc = Ss[r];
                v.x = fmaxf((v.x - Ms[k0 + c4 * 4 + 0]) * sc, 0.f);
                v.y = fmaxf((v.y - Ms[k0 + c4 * 4 + 1]) * sc, 0.f);
                v.z = fmaxf((v.z - Ms[k0 + c4 * 4 + 2]) * sc, 0.f);
                v.w = fmaxf((v.w - Ms[k0 + c4 * 4 + 3]) * sc, 0.f);
            }
            u64 d0, d1, d2, d3;
            asm("mov.b64 %0, {%1, %1};" : "=l"(d0) : "f"(v.x));
            asm("mov.b64 %0, {%1, %1};" : "=l"(d1) : "f"(v.y));
            asm("mov.b64 %0, {%1, %1};" : "=l"(d2) : "f"(v.z));
            asm("mov.b64 %0, {%1, %1};" : "=l"(d3) : "f"(v.w));
            As2[c4 * 4 + 0][r] = d0;
            As2[c4 * 4 + 1][r] = d1;
            As2[c4 * 4 + 2][r] = d2;
            As2[c4 * 4 + 3][r] = d3;
        }
        // W tile: BK x OW floats
#pragma unroll
        for (int i = t; i < BK * OW; i += 256) {
            int r = i / OW, c = i % OW;
            Ws[r][c] = W[(k0 + r) * OW + c];
        }
        __syncthreads();
#pragma unroll
        for (int kk = 0; kk < BK; kk++) {
            u64 wv2[4];
#pragma unroll
            for (int j = 0; j < 4; j++)
                wv2[j] = *(const u64*)&Ws[kk][2 * tx + j * 2 * CT];
            u64 av2[RPT];
#pragma unroll
            for (int i = 0; i < RPT / 2; i++) {
                ulonglong2 p = *(const ulonglong2*)&As2[kk][ty * RPT + 2 * i];
                av2[2 * i] = p.x;
                av2[2 * i + 1] = p.y;
            }
#pragma unroll
            for (int r = 0; r < RPT; r++)
#pragma unroll
                for (int j = 0; j < 4; j++)
                    asm("fma.rn.f32x2 %0, %1, %2, %0;" : "+l"(acc2[r][j]) : "l"(av2[r]), "l"(wv2[j]));
        }
        __syncthreads();
    }

    // epilogue: fp16 store + attention dots (shuffle-reduced over CT lanes)
    float2 av[4], bv[4];
#pragma unroll
    for (int j = 0; j < 4; j++) {
        av[j] = ((const float2*)asrc)[tx + j * CT];
        bv[j] = ((const float2*)adst)[tx + j * CT];
    }

#pragma unroll
    for (int r = 0; r < RPT; r++) {
        int gr = row0 + ty * RPT + r;
        float s0 = 0.f, d0 = 0.f, s1 = 0.f, d1 = 0.f;
        __half2 c2[4];
#pragma unroll
        for (int j = 0; j < 4; j++) {
            float lo, hi;
            asm("mov.b64 {%0, %1}, %2;" : "=f"(lo), "=f"(hi) : "l"(acc2[r][j]));
            c2[j] = __float22half2_rn(make_float2(lo, hi));
            if (j < 2) {
                s0 = fmaf(lo, av[j].x, fmaf(hi, av[j].y, s0));
                d0 = fmaf(lo, bv[j].x, fmaf(hi, bv[j].y, d0));
            } else {
                s1 = fmaf(lo, av[j].x, fmaf(hi, av[j].y, s1));
                d1 = fmaf(lo, bv[j].x, fmaf(hi, bv[j].y, d1));
            }
        }
        if (gr < N) {
#pragma unroll
            for (int j = 0; j < 4; j++)
                ((__half2*)&C[(size_t)gr * OW])[tx + j * CT] = c2[j];
        }
#pragma unroll
        for (int o = CT / 2; o > 0; o >>= 1) {
            s0 += __shfl_down_sync(0xffffffffu, s0, o, CT);
            d0 += __shfl_down_sync(0xffffffffu, d0, o, CT);
            s1 += __shfl_down_sync(0xffffffffu, s1, o, CT);
            d1 += __shfl_down_sync(0xffffffffu, d1, o, CT);
        }
        if (tx == 0 && gr < N) {
            als[gr * 2 + 0] = s0;
            als[gr * 2 + 1] = s1;
            ald[gr * 2 + 0] = d0;
            ald[gr * 2 + 1] = d1;
        }
    }
}

// ---------------------------------------------------------------------------
// Softmax aggregation, precomputed weights, fp16 features, 16B per lane:
// HD=128: L=16 lanes/node (uint4 = 8 halves each), 2 nodes/warp.
// HD=32 (FINAL): L=4 lanes/node, 8 nodes/warp; head-mean + bias -> d_out.
// Fused column-sum for non-FINAL layers.
// ---------------------------------------------------------------------------
template <int HD, bool FINAL>
__global__ void __launch_bounds__(256)
aggr_kernel(const __half* __restrict__ xh,
            const float2* __restrict__ w2,
            const int* __restrict__ off, const int* __restrict__ csr,
            const float* __restrict__ bias,
            float* __restrict__ out, float* __restrict__ cs, int N) {
    constexpr int L = (HD * 2) / 16;   // lanes per node: 16 (HD=128) or 4 (HD=32)
    constexpr int NPW = 32 / L;        // nodes per warp: 2 or 8
    constexpr int D = HD / 2;          // features per head
    int wib = threadIdx.x >> 5;
    int wid = blockIdx.x * 8 + wib;
    int lane = threadIdx.x & 31;
    int sub = lane / L;
    int lig = lane % L;
    int nreq = wid * NPW + sub;
    bool valid = nreq < N;
    int n = valid ? nreq : (N - 1);

    int st = off[n], en = off[n + 1];
    int head = (lig * 8) / D;          // 8 features per lane

    float s0 = 0.f, s1 = 0.f;
    float acc[8];
#pragma unroll
    for (int k = 0; k < 8; k++) acc[k] = 0.f;
    const uint4* x16 = (const uint4*)xh;   // row stride = L uint4s

#pragma unroll 4
    for (int i = st; i < en; i++) {
        int s = csr[i];
        float2 w = w2[i];
        s0 += w.x; s1 += w.y;
        float ws = head ? w.y : w.x;
        uint4 u = x16[(size_t)s * L + lig];
        float2 f0 = __half22float2(*(__half2*)&u.x);
        float2 f1 = __half22float2(*(__half2*)&u.y);
        float2 f2 = __half22float2(*(__half2*)&u.z);
        float2 f3 = __half22float2(*(__half2*)&u.w);
        acc[0] = fmaf(ws, f0.x, acc[0]);
        acc[1] = fmaf(ws, f0.y, acc[1]);
        acc[2] = fmaf(ws, f1.x, acc[2]);
        acc[3] = fmaf(ws, f1.y, acc[3]);
        acc[4] = fmaf(ws, f2.x, acc[4]);
        acc[5] = fmaf(ws, f2.y, acc[5]);
        acc[6] = fmaf(ws, f3.x, acc[6]);
        acc[7] = fmaf(ws, f3.y, acc[7]);
    }
    float inv = 1.0f / (head ? s1 : s0);
#pragma unroll
    for (int k = 0; k < 8; k++) acc[k] *= inv;

    if (FINAL) {
        // L=4: lanes lig<2 hold head0 feats, lig>=2 head1 (partner = lane+2).
        float o[8];
#pragma unroll
        for (int k = 0; k < 8; k++) o[k] = __shfl_down_sync(0xffffffffu, acc[k], 2);
        if (valid && lig < 2) {
            float4 r0, r1;
            r0.x = 0.5f * (acc[0] + o[0]) + bias[lig * 8 + 0];
            r0.y = 0.5f * (acc[1] + o[1]) + bias[lig * 8 + 1];
            r0.z = 0.5f * (acc[2] + o[2]) + bias[lig * 8 + 2];
            r0.w = 0.5f * (acc[3] + o[3]) + bias[lig * 8 + 3];
            r1.x = 0.5f * (acc[4] + o[4]) + bias[lig * 8 + 4];
            r1.y = 0.5f * (acc[5] + o[5]) + bias[lig * 8 + 5];
            r1.z = 0.5f * (acc[6] + o[6]) + bias[lig * 8 + 6];
            r1.w = 0.5f * (acc[7] + o[7]) + bias[lig * 8 + 7];
            float4* dst = (float4*)&out[(size_t)n * 16 + lig * 8];
            dst[0] = r0;
            dst[1] = r1;
        }
    } else {
        if (valid) {
            float4* dst = (float4*)&out[(size_t)n * 128 + lig * 8];
            dst[0] = make_float4(acc[0], acc[1], acc[2], acc[3]);
            dst[1] = make_float4(acc[4], acc[5], acc[6], acc[7]);
        }
        __shared__ float csm[16][128];
        float* rowp = csm[wib * 2 + sub];
        if (!valid) {
#pragma unroll
            for (int k = 0; k < 8; k++) acc[k] = 0.f;
        }
        ((float4*)&rowp[lig * 8])[0] = make_float4(acc[0], acc[1], acc[2], acc[3]);
        ((float4*)&rowp[lig * 8])[1] = make_float4(acc[4], acc[5], acc[6], acc[7]);
        __syncthreads();
        int t = threadIdx.x;
        if (t < 128) {
            float s = 0.f;
#pragma unroll
            for (int w = 0; w < 16; w++) s += csm[w][t];
            atomicAdd(&cs[t], s);
        }
    }
}

// ---------------------------------------------------------------------------
// Per-row PairNorm scale: scale[n] = 1/(eps + ||row - mean||)
// ---------------------------------------------------------------------------
__global__ void pnscale_kernel(const float* __restrict__ in, const float* __restrict__ cs,
                               float* __restrict__ scale, int N) {
    int wid = (blockIdx.x * blockDim.x + threadIdx.x) >> 5;
    int lane = threadIdx.x & 31;
    if (wid >= N) return;
    float invN = 1.0f / (float)N;
    float4 m = ((const float4*)cs)[lane];
    float4 v = ((const float4*)in)[(size_t)wid * 32 + lane];
    v.x -= m.x * invN; v.y -= m.y * invN; v.z -= m.z * invN; v.w -= m.w * invN;
    float n2 = v.x * v.x + v.y * v.y + v.z * v.z + v.w * v.w;
#pragma unroll
    for (int o = 16; o > 0; o >>= 1) n2 += __shfl_xor_sync(0xffffffffu, n2, o);
    if (lane == 0) scale[wid] = 1.0f / (1e-5f + sqrtf(n2));
}

// ---------------------------------------------------------------------------
extern "C" void kernel_launch(void* const* d_in, const int* in_sizes, int n_in,
                              void* d_out, int out_size) {
    const float* x   = (const float*)d_in[0];
    const void*  ei  = d_in[1];
    const float* W1  = (const float*)d_in[2];
    const float* as1 = (const float*)d_in[3];
    const float* ad1 = (const float*)d_in[4];
    const float* W2  = (const float*)d_in[6];
    const float* as2 = (const float*)d_in[7];
    const float* ad2 = (const float*)d_in[8];
    const float* W3  = (const float*)d_in[10];
    const float* as3 = (const float*)d_in[11];
    const float* ad3 = (const float*)d_in[12];
    const float* b3  = (const float*)d_in[13];

    int N = in_sizes[0] / 128;
    int E = in_sizes[1] / 2;
    int Etot = E + N;

    __half* xh;
    float *agg, *als, *ald, *scl, *cs;
    float2* w2;
    int *cnt, *off, *cur, *csr, *dste, *bsum, *bpre;
    cudaGetSymbolAddress((void**)&xh, g_xh);
    cudaGetSymbolAddress((void**)&agg, g_agg);
    cudaGetSymbolAddress((void**)&als, g_als);
    cudaGetSymbolAddress((void**)&ald, g_ald);
    cudaGetSymbolAddress((void**)&scl, g_scale);
    cudaGetSymbolAddress((void**)&cs, g_cs);
    cudaGetSymbolAddress((void**)&w2, g_w2);
    cudaGetSymbolAddress((void**)&cnt, g_cnt);
    cudaGetSymbolAddress((void**)&off, g_off);
    cudaGetSymbolAddress((void**)&cur, g_cur);
    cudaGetSymbolAddress((void**)&csr, g_csr);
    cudaGetSymbolAddress((void**)&dste, g_dste);
    cudaGetSymbolAddress((void**)&bsum, g_bsum);
    cudaGetSymbolAddress((void**)&bpre, g_bpre);
    float* cs0 = cs;
    float* cs1 = cs + 128;

    const int TB = 256;
    int aggr_blocks   = (N / 2 + 7) / 8;   // 2 nodes/warp, 8 warps/block
    int aggr_blocks8  = (N / 8 + 7) / 8;   // 8 nodes/warp (layer 3)
    int pn_blocks     = (N + 7) / 8;
    int gemm_blocks   = (N + 127) / 128;
    int nb1 = (N + 255) / 256;             // 196 <= 256

    cudaMemsetAsync(cnt, 0, (size_t)N * sizeof(int));

    // ---- launch 0: histogram (embeds dtype probe) ----
    hist_kernel<<<(Etot + TB - 1) / TB, TB>>>(ei, E, Etot, N, cnt);
    // ---- launches 1-2: scan front ----
    scan_bsum_kernel<<<nb1, 256>>>(cnt, bsum, N);
    scan_bscan_kernel<<<1, 256>>>(bsum, bpre, off, nb1, N);
    // ---- launch 3: GEMM layer 1  <- ncu capture window ----
    gemm_attn_kernel<128, false><<<gemm_blocks, TB>>>(x, nullptr, nullptr, W1, as1, ad1,
                                                      xh, als, ald, cs0, N);
    // ---- launches 4-5: finish CSR (scatter also computes layer-1 weights) ----
    scan_write_kernel<<<nb1, 256>>>(cnt, bpre, off, cur, N);
    scatter_kernel<<<(Etot + TB - 1) / TB, TB>>>(ei, E, Etot, cur, csr, dste, als, ald, w2);

    // ---- layer 1 aggregation + pairnorm scale ----
    aggr_kernel<128, false><<<aggr_blocks, TB>>>(xh, w2, off, csr, nullptr, agg, cs0, N);
    pnscale_kernel<<<pn_blocks, TB>>>(agg, cs0, scl, N);

    // ---- layer 2 ----
    gemm_attn_kernel<128, true><<<gemm_blocks, TB>>>(agg, cs0, scl, W2, as2, ad2,
                                                     xh, als, ald, cs1, N);
    ew_kernel<<<(Etot + TB - 1) / TB, TB>>>(csr, dste, als, ald, w2, Etot);
    aggr_kernel<128, false><<<aggr_blocks, TB>>>(xh, w2, off, csr, nullptr, agg, cs1, N);
    pnscale_kernel<<<pn_blocks, TB>>>(agg, cs1, scl, N);

    // ---- layer 3 (writes d_out with head-mean + bias) ----
    gemm_attn_kernel<32, true><<<gemm_blocks, TB>>>(agg, cs1, scl, W3, as3, ad3,
                                                    xh, als, ald, nullptr, N);
    ew_kernel<<<(Etot + TB - 1) / TB, TB>>>(csr, dste, als, ald, w2, Etot);
    aggr_kernel<32, true><<<aggr_blocks8, TB>>>(xh, w2, off, csr, b3,
                                                (float*)d_out, nullptr, N);
}